// round 12
// baseline (speedup 1.0000x reference)
#include <cuda_runtime.h>
#include <cuda_fp16.h>
#include <cstdint>

#define LEVELS 18
#define NNODES ((1 << LEVELS) - 1)
#define LEAF_START ((1 << (LEVELS - 1)) - 1)   // 131071
#define LEAF_COUNT (1 << (LEVELS - 1))         // 131072

// Persisted state + preconverted weights (device globals; no runtime alloc).
__device__ float  g_c  [(size_t)NNODES * 64];   // cell state, cols 0..63 only
__device__ __half g_hh [(size_t)NNODES * 64];   // h fp16, cols 0..63
__device__ __half g_GX [(size_t)(NNODES + 1) * 512]; // W_ih*x + b, fp16
__device__ __half g_Wx [512 * 64];              // [gate][k] W_ih fp16
__device__ __half g_Wh [512 * 128];             // [gate][k] W_hh fp16
__device__ float  g_bsum[512];

// ------------------------------------------------------------------ helpers
__device__ __forceinline__ uint32_t smem_u32(const void* p) {
    uint32_t a;
    asm("{ .reg .u64 t; cvta.to.shared.u64 t, %1; cvt.u32.u64 %0, t; }"
        : "=r"(a) : "l"(p));
    return a;
}
__device__ __forceinline__ void ldsm_x4(uint32_t* r, uint32_t addr) {
    asm volatile("ldmatrix.sync.aligned.m8n8.x4.shared.b16 {%0,%1,%2,%3}, [%4];"
                 : "=r"(r[0]), "=r"(r[1]), "=r"(r[2]), "=r"(r[3]) : "r"(addr));
}
__device__ __forceinline__ void mma_f16(float* d, const uint32_t* a, const uint32_t* b) {
    asm volatile("mma.sync.aligned.m16n8k16.row.col.f32.f16.f16.f32 "
                 "{%0,%1,%2,%3}, {%4,%5,%6,%7}, {%8,%9}, {%0,%1,%2,%3};"
                 : "+f"(d[0]), "+f"(d[1]), "+f"(d[2]), "+f"(d[3])
                 : "r"(a[0]), "r"(a[1]), "r"(a[2]), "r"(a[3]), "r"(b[0]), "r"(b[1]));
}
__device__ __forceinline__ void cp_async16(uint32_t saddr, const void* g) {
    asm volatile("cp.async.ca.shared.global [%0], [%1], 16;"
                 :: "r"(saddr), "l"(g) : "memory");
}
__device__ __forceinline__ void cp_async_commit() {
    asm volatile("cp.async.commit_group;" ::: "memory");
}
__device__ __forceinline__ float tanhfast(float z) {
    float r;
    asm("tanh.approx.f32 %0, %1;" : "=f"(r) : "f"(z));
    return r;
}
__device__ __forceinline__ float sigf(float z) {
    return fmaf(tanhfast(0.5f * z), 0.5f, 0.5f);
}

// ---------------------------------------------------------------- prep
__global__ void prep_kernel(const float* __restrict__ Wih,
                            const float* __restrict__ Whh,
                            const float* __restrict__ bih,
                            const float* __restrict__ bhh)
{
    int idx = blockIdx.x * blockDim.x + threadIdx.x;
    int stride = gridDim.x * blockDim.x;
    if (idx < 512) g_bsum[idx] = bih[idx] + bhh[idx];
    for (int p = idx; p < 512 * 64; p += stride)
        g_Wx[p] = __float2half_rn(Wih[p]);
    for (int p = idx; p < 512 * 128; p += stride)
        g_Wh[p] = __float2half_rn(Whh[p]);
}

// =====================================================================
// x-GEMM: GX[n][g] = W_ih[g]·x[n] + bsum[g], all 262143 nodes (+1 pad).
// CTA = 128 nodes x 512 gates (8 chunks of 64), 256 threads,
// 8 warps = 4 row-groups (32 nodes) x 2 chunk-halves. K=64 (2 dk).
// =====================================================================
#define RS3 144
#define XG_A    2048
#define XG_B    (XG_A + 128 * RS3)      // 20480; two buffers of 9216
#define XG_BUF  9216
#define SMEM_XG (XG_B + 2 * XG_BUF)     // 38912 -> 3+ CTAs/SM

__global__ __launch_bounds__(256, 3)
void xgemm_kernel(const float* __restrict__ x)
{
    extern __shared__ __align__(16) char smem[];
    const uint32_t sb = smem_u32(smem);
    const int tid = threadIdx.x;
    const int lane = tid & 31;
    const int rg = (tid >> 5) & 3;
    const int ch = tid >> 7;
    const int tileBase = blockIdx.x * 128;

    float* bs = (float*)smem;           // bias at XG_A-2048.. use offset 0
    for (int i = tid; i < 512; i += 256) bs[i] = g_bsum[i];

    // A: [128 rows][64 k] fp16 (convert; guard the single pad node)
    #pragma unroll
    for (int it = 0; it < 16; ++it) {
        int p = tid + it * 256;
        int row = p >> 5;
        int kp  = (p & 31) * 2;
        int gnode = tileBase + row;
        __half2 hp = {__float2half_rn(0.f), __float2half_rn(0.f)};
        if (gnode < NNODES) {
            float2 xv = *(const float2*)(x + (size_t)gnode * 64 + kp);
            hp = {__float2half_rn(xv.x), __float2half_rn(xv.y)};
        }
        *(uint32_t*)(smem + XG_A + row * RS3 + kp * 2) = *(uint32_t*)&hp;
    }

    auto issue_b = [&](int nc, int buf) {
        uint32_t bo = sb + XG_B + (uint32_t)buf * XG_BUF;
        #pragma unroll
        for (int it = 0; it < 2; ++it) {
            int p = tid + it * 256;                 // p < 512: 64 rows x 8
            int rr = p >> 3, u = p & 7;
            int j = rr >> 3, w = rr & 7;
            int gate = ((j & 3) << 7) + (nc << 4) + ((j >> 2) << 3) + w;
            cp_async16(bo + (uint32_t)(rr * RS3 + u * 16),
                       g_Wx + (size_t)gate * 64 + u * 8);
        }
    };
    issue_b(0, 0);
    cp_async_commit();

    const uint32_t aBase = sb + XG_A +
        (uint32_t)((rg * 32 + (lane & 15)) * RS3 + ((lane >> 4) << 4));
    const uint32_t bBase = sb + XG_B +
        (uint32_t)(ch * 32 * RS3 + (lane & 7) * RS3 + ((lane >> 3) << 4));
    const int r0   = rg * 32 + (lane >> 2);
    const int huL0 = (lane & 3) * 2;

    for (int nc = 0; nc < 8; ++nc) {
        asm volatile("cp.async.wait_group 0;" ::: "memory");
        __syncthreads();
        if (nc < 7) { issue_b(nc + 1, (nc + 1) & 1); cp_async_commit(); }

        const uint32_t bHi = bBase + (uint32_t)(nc & 1) * XG_BUF;

        float acc[2][4][4];
        #pragma unroll
        for (int m = 0; m < 2; ++m)
            #pragma unroll
            for (int j = 0; j < 4; ++j)
                #pragma unroll
                for (int c = 0; c < 4; ++c) acc[m][j][c] = 0.f;

        #pragma unroll
        for (int dk = 0; dk < 2; ++dk) {
            uint32_t a0[2][4], a1[2][4];
            #pragma unroll
            for (int m = 0; m < 2; ++m) {
                ldsm_x4(a0[m], aBase + m * (16 * RS3) + dk * 64);
                ldsm_x4(a1[m], aBase + m * (16 * RS3) + dk * 64 + 32);
            }
            #pragma unroll
            for (int jj = 0; jj < 4; ++jj) {
                uint32_t bh[4];
                ldsm_x4(bh, bHi + jj * (8 * RS3) + dk * 64);
                #pragma unroll
                for (int m = 0; m < 2; ++m) {
                    mma_f16(acc[m][jj], a0[m], bh);
                    mma_f16(acc[m][jj], a1[m], bh + 2);
                }
            }
        }

        // store GX (+bias), fp16
        #pragma unroll
        for (int m = 0; m < 2; ++m) {
            #pragma unroll
            for (int rh = 0; rh < 2; ++rh) {
                int row = r0 + m * 16 + 8 * rh;
                int gnode = tileBase + row;
                if (gnode < NNODES) {
                    #pragma unroll
                    for (int jj = 0; jj < 4; ++jj) {
                        int g0 = (jj << 7) + (nc << 4) + (ch << 3) + huL0;
                        __half2 v = {__float2half_rn(acc[m][jj][2*rh]   + bs[g0]),
                                     __float2half_rn(acc[m][jj][2*rh+1] + bs[g0+1])};
                        *(uint32_t*)(g_GX + (size_t)gnode * 512 + g0) = *(uint32_t*)&v;
                    }
                }
            }
        }
        __syncthreads();
    }
}

// =====================================================================
// Leaf epilogue: gates = GX (c_prev = h_prev = 0). Pure streaming.
// Block = 256 threads = 16 nodes; thread covers 8 hu of one node.
// =====================================================================
__global__ __launch_bounds__(256, 6)
void leaf_epi_kernel(float* __restrict__ out)
{
    const int t = threadIdx.x;
    const int n = LEAF_START + blockIdx.x * 16 + (t >> 4);
    const int hu0 = (t & 15) * 8;
    const __half* gx = g_GX + (size_t)n * 512;

    uint4 ri = *(const uint4*)(gx + hu0);
    uint4 rf = *(const uint4*)(gx + 128 + hu0);
    uint4 rg = *(const uint4*)(gx + 256 + hu0);
    uint4 ro = *(const uint4*)(gx + 384 + hu0);
    const __half2* hi = (const __half2*)&ri;
    const __half2* hf = (const __half2*)&rf;
    const __half2* hg = (const __half2*)&rg;
    const __half2* ho = (const __half2*)&ro;

    float hbuf[8], cbuf[8];
    __half hh[8];
    #pragma unroll
    for (int q = 0; q < 4; ++q) {
        float2 vi = __half22float2(hi[q]);
        float2 vf = __half22float2(hf[q]);
        float2 vg = __half22float2(hg[q]);
        float2 vo = __half22float2(ho[q]);
        float c0 = sigf(vi.x) * tanhfast(vg.x);
        float c1 = sigf(vi.y) * tanhfast(vg.y);
        (void)vf;
        float h0 = sigf(vo.x) * tanhfast(c0);
        float h1 = sigf(vo.y) * tanhfast(c1);
        hbuf[2*q] = h0; hbuf[2*q+1] = h1;
        cbuf[2*q] = c0; cbuf[2*q+1] = c1;
        hh[2*q] = __float2half_rn(h0); hh[2*q+1] = __float2half_rn(h1);
    }
    *(float4*)(out + (size_t)n * 128 + hu0)     = *(float4*)&hbuf[0];
    *(float4*)(out + (size_t)n * 128 + hu0 + 4) = *(float4*)&hbuf[4];
    if (hu0 < 64) {
        *(float4*)(g_c + (size_t)n * 64 + hu0)     = *(float4*)&cbuf[0];
        *(float4*)(g_c + (size_t)n * 64 + hu0 + 4) = *(float4*)&cbuf[4];
        *(uint4*)(g_hh + (size_t)n * 64 + hu0) = *(uint4*)hh;
    }
}

// =====================================================================
// Inner tc kernel: gates = GX + W_hh*h_prev. K = 128 (4 dk).
// CTA = 128 nodes x (512/gs) gates, 256 threads, 8 warps, 3 CTAs/SM.
// =====================================================================
#define RS2 272
#define IN_A   0
#define IN_B   (128 * RS2)              // 34816; two buffers of 17408
#define IN_BUF 17408
#define SMEM_IN (IN_B + 2 * IN_BUF)     // 69632 -> 3 CTAs/SM (24 warps)

__global__ __launch_bounds__(256, 3)
void lstm_tc_kernel(float* __restrict__ out,
                    int start, int tiles, int cpc)
{
    extern __shared__ __align__(16) char smem[];
    const uint32_t sb = smem_u32(smem);
    const int tid = threadIdx.x;
    const int lane = tid & 31;
    const int rg = (tid >> 5) & 3;
    const int ch = tid >> 7;
    const int tile = blockIdx.x % tiles;
    const int nc0  = (blockIdx.x / tiles) * cpc;
    const int tileBase = tile * 128;

    // A: h_prev [128 rows][128 k] fp16, via cp.async gather
    #pragma unroll
    for (int it = 0; it < 8; ++it) {
        int p = tid + it * 256;
        int row = p >> 4;
        int u   = p & 15;                // 0..7 left, 8..15 right
        int gnode = start + tileBase + row;
        int child = (u < 8) ? (2 * gnode + 1) : (2 * gnode + 2);
        int uu = u & 7;
        cp_async16(sb + IN_A + (uint32_t)(row * RS2 + u * 16),
                   g_hh + (size_t)child * 64 + uu * 8);
    }

    auto issue_b = [&](int nc, int buf) {
        uint32_t bo = sb + IN_B + (uint32_t)buf * IN_BUF;
        #pragma unroll
        for (int it = 0; it < 4; ++it) {
            int p = tid + it * 256;                 // p < 1024: 64 rows x 16
            int rr = p >> 4, u = p & 15;
            int j = rr >> 3, w = rr & 7;
            int gate = ((j & 3) << 7) + (nc << 4) + ((j >> 2) << 3) + w;
            cp_async16(bo + (uint32_t)(rr * RS2 + u * 16),
                       g_Wh + (size_t)gate * 128 + u * 8);
        }
    };
    issue_b(nc0, 0);
    cp_async_commit();

    const uint32_t aBase = sb + IN_A +
        (uint32_t)((rg * 32 + (lane & 15)) * RS2 + ((lane >> 4) << 4));
    const uint32_t bBase = sb + IN_B +
        (uint32_t)(ch * 32 * RS2 + (lane & 7) * RS2 + ((lane >> 3) << 4));
    const int r0   = rg * 32 + (lane >> 2);
    const int huL0 = (lane & 3) * 2;

    for (int l = 0; l < cpc; ++l) {
        const int nc = nc0 + l;
        asm volatile("cp.async.wait_group 0;" ::: "memory");
        __syncthreads();
        if (l + 1 < cpc) { issue_b(nc + 1, (l + 1) & 1); cp_async_commit(); }

        const uint32_t bHi = bBase + (uint32_t)(l & 1) * IN_BUF;

        float acc[2][4][4];
        #pragma unroll
        for (int m = 0; m < 2; ++m)
            #pragma unroll
            for (int j = 0; j < 4; ++j)
                #pragma unroll
                for (int c = 0; c < 4; ++c) acc[m][j][c] = 0.f;

        #pragma unroll
        for (int dk = 0; dk < 4; ++dk) {
            uint32_t a0[2][4], a1[2][4];
            #pragma unroll
            for (int m = 0; m < 2; ++m) {
                ldsm_x4(a0[m], aBase + m * (16 * RS2) + dk * 64);
                ldsm_x4(a1[m], aBase + m * (16 * RS2) + dk * 64 + 32);
            }
            #pragma unroll
            for (int jj = 0; jj < 4; ++jj) {
                uint32_t bh[4];
                ldsm_x4(bh, bHi + jj * (8 * RS2) + dk * 64);
                #pragma unroll
                for (int m = 0; m < 2; ++m) {
                    mma_f16(acc[m][jj], a0[m], bh);
                    mma_f16(acc[m][jj], a1[m], bh + 2);
                }
            }
        }

        // ---- fused LSTM epilogue: gates = acc + GX (bias folded in) ----
        const int hu = (nc << 4) + (ch << 3) + huL0;
        #pragma unroll
        for (int m = 0; m < 2; ++m) {
            #pragma unroll
            for (int rh = 0; rh < 2; ++rh) {
                const int row = r0 + m * 16 + 8 * rh;
                const int gnode = start + tileBase + row;
                const __half* gx = g_GX + (size_t)gnode * 512;
                int child = (hu < 64) ? (2 * gnode + 1) : (2 * gnode + 2);
                float2 cp = *(const float2*)(g_c + (size_t)child * 64 + (hu & 63));
                float2 xi = __half22float2(*(const __half2*)(gx + hu));
                float2 xf = __half22float2(*(const __half2*)(gx + 128 + hu));
                float2 xg = __half22float2(*(const __half2*)(gx + 256 + hu));
                float2 xo = __half22float2(*(const __half2*)(gx + 384 + hu));
                float gi0 = acc[m][0][2*rh]   + xi.x;
                float gi1 = acc[m][0][2*rh+1] + xi.y;
                float gf0 = acc[m][1][2*rh]   + xf.x;
                float gf1 = acc[m][1][2*rh+1] + xf.y;
                float gg0 = acc[m][2][2*rh]   + xg.x;
                float gg1 = acc[m][2][2*rh+1] + xg.y;
                float go0 = acc[m][3][2*rh]   + xo.x;
                float go1 = acc[m][3][2*rh+1] + xo.y;
                float c0 = sigf(gf0) * cp.x + sigf(gi0) * tanhfast(gg0);
                float c1 = sigf(gf1) * cp.y + sigf(gi1) * tanhfast(gg1);
                float h0 = sigf(go0) * tanhfast(c0);
                float h1 = sigf(go1) * tanhfast(c1);
                *(float2*)(out + (size_t)gnode * 128 + hu) = make_float2(h0, h1);
                if (hu < 64) {
                    *(float2*)(g_c + (size_t)gnode * 64 + hu) = make_float2(c0, c1);
                    __half2 hp = {__float2half_rn(h0), __float2half_rn(h1)};
                    *(uint32_t*)(g_hh + (size_t)gnode * 64 + hu) = *(uint32_t*)&hp;
                }
            }
        }
    }
}

// =====================================================================
// Small-level SIMT kernel: 8 nodes per 256-thread block, K=128 (h only).
// acc init from GX (bias folded in).
// =====================================================================
__global__ __launch_bounds__(256, 4)
void lstm_small_kernel(const float* __restrict__ Whh,
                       float* __restrict__ out,
                       int start, int count)
{
    __shared__ __align__(16) float As[8][132];
    __shared__ __align__(16) float Cs[8][128];

    const int t = threadIdx.x;
    const int tileBase = blockIdx.x * 8;

    {
        int node = t / 32, col = (t & 31) * 4;
        float4 vh = make_float4(0.f, 0.f, 0.f, 0.f);
        float4 vc = make_float4(0.f, 0.f, 0.f, 0.f);
        int nodeIdx = tileBase + node;
        if (nodeIdx < count) {
            int gnode = start + nodeIdx;
            int child = (col < 64) ? (2 * gnode + 1) : (2 * gnode + 2);
            int cc    = (col < 64) ? col : (col - 64);
            vh = *(const float4*)(out + (size_t)child * 128 + cc);
            vc = *(const float4*)(g_c + (size_t)child * 64 + cc);
        }
        *(float4*)&As[node][col] = vh;
        *(float4*)&Cs[node][col] = vc;
    }
    __syncthreads();

    const int hu = t & 127;
    const int np = t >> 7;
    float acc[4][4];
    #pragma unroll
    for (int n = 0; n < 4; ++n) {
        int nodeIdx = tileBase + np + 2 * n;
        int gnode = start + min(nodeIdx, count - 1);
        #pragma unroll
        for (int g = 0; g < 4; ++g)
            acc[n][g] = __half2float(g_GX[(size_t)gnode * 512 + hu + g * 128]);
    }

    for (int kc = 0; kc < 32; ++kc) {
        const int k0 = kc * 4;
        float4 w[4];
        #pragma unroll
        for (int g = 0; g < 4; ++g)
            w[g] = *(const float4*)(Whh + (size_t)(hu + g * 128) * 128 + k0);
        #pragma unroll
        for (int n = 0; n < 4; ++n) {
            float4 a = *(const float4*)&As[np + 2 * n][k0];
            #pragma unroll
            for (int g = 0; g < 4; ++g)
                acc[n][g] += a.x * w[g].x + a.y * w[g].y + a.z * w[g].z + a.w * w[g].w;
        }
    }

    #pragma unroll
    for (int n = 0; n < 4; ++n) {
        int nn = np + 2 * n;
        int nodeIdx = tileBase + nn;
        if (nodeIdx < count) {
            int gnode = start + nodeIdx;
            float cpv = Cs[nn][hu];
            float c = sigf(acc[n][1]) * cpv + sigf(acc[n][0]) * tanhfast(acc[n][2]);
            float h = sigf(acc[n][3]) * tanhfast(c);
            out[(size_t)gnode * 128 + hu] = h;
            if (hu < 64) g_c[(size_t)gnode * 64 + hu] = c;
        }
    }
}

extern "C" void kernel_launch(void* const* d_in, const int* in_sizes, int n_in,
                              void* d_out, int out_size)
{
    const float* x   = (const float*)d_in[0];   // [262143, 64]
    const float* Wih = (const float*)d_in[1];   // [512, 64]
    const float* Whh = (const float*)d_in[2];   // [512, 128]
    const float* bih = (const float*)d_in[3];   // [512]
    const float* bhh = (const float*)d_in[4];   // [512]
    float* out = (float*)d_out;                 // [262143, 128]

    static bool attr_done = false;
    if (!attr_done) {
        cudaFuncSetAttribute(lstm_tc_kernel,
                             cudaFuncAttributeMaxDynamicSharedMemorySize, SMEM_IN);
        cudaFuncSetAttribute(xgemm_kernel,
                             cudaFuncAttributeMaxDynamicSharedMemorySize, SMEM_XG);
        attr_done = true;
    }

    prep_kernel<<<148, 256>>>(Wih, Whh, bih, bhh);
    xgemm_kernel<<<2048, 256, SMEM_XG>>>(x);              // GX for all nodes
    leaf_epi_kernel<<<LEAF_COUNT / 16, 256>>>(out);       // level 17

    const int CONC = 444;   // 148 SMs x 3 CTAs
    for (int lvl = LEVELS - 2; lvl >= 0; --lvl) {
        int start = (1 << lvl) - 1;
        int count = 1 << lvl;
        if (count >= 1024) {
            int tiles = count / 128;
            int gs = 1;
            while (gs < 8 && tiles * gs * 3 <= CONC) gs <<= 1;
            lstm_tc_kernel<<<tiles * gs, 256, SMEM_IN>>>(
                out, start, tiles, 8 / gs);
        } else {
            lstm_small_kernel<<<(count + 7) / 8, 256>>>(Whh, out, start, count);
        }
    }
}

// round 13
// speedup vs baseline: 1.2354x; 1.2354x over previous
#include <cuda_runtime.h>
#include <cuda_fp16.h>
#include <cstdint>

#define LEVELS 18
#define NNODES ((1 << LEVELS) - 1)

// Persisted state + preconverted weights (device globals; no runtime alloc).
__device__ float  g_c [(size_t)NNODES * 64];   // cell state, cols 0..63 only
__device__ __half g_hh[(size_t)NNODES * 64];   // h fp16, cols 0..63
__device__ __half g_W [512 * 192];             // [gate][k] concat(Wih,Whh) fp16
__device__ float  g_bsum[512];

// ------------------------------------------------------------------ helpers
__device__ __forceinline__ uint32_t smem_u32(const void* p) {
    uint32_t a;
    asm("{ .reg .u64 t; cvta.to.shared.u64 t, %1; cvt.u32.u64 %0, t; }"
        : "=r"(a) : "l"(p));
    return a;
}
__device__ __forceinline__ void ldsm_x4(uint32_t* r, uint32_t addr) {
    asm volatile("ldmatrix.sync.aligned.m8n8.x4.shared.b16 {%0,%1,%2,%3}, [%4];"
                 : "=r"(r[0]), "=r"(r[1]), "=r"(r[2]), "=r"(r[3]) : "r"(addr));
}
__device__ __forceinline__ void mma_f16(float* d, const uint32_t* a, const uint32_t* b) {
    asm volatile("mma.sync.aligned.m16n8k16.row.col.f32.f16.f16.f32 "
                 "{%0,%1,%2,%3}, {%4,%5,%6,%7}, {%8,%9}, {%0,%1,%2,%3};"
                 : "+f"(d[0]), "+f"(d[1]), "+f"(d[2]), "+f"(d[3])
                 : "r"(a[0]), "r"(a[1]), "r"(a[2]), "r"(a[3]), "r"(b[0]), "r"(b[1]));
}
__device__ __forceinline__ void cp_async16(uint32_t saddr, const void* g) {
    asm volatile("cp.async.ca.shared.global [%0], [%1], 16;"
                 :: "r"(saddr), "l"(g) : "memory");
}
__device__ __forceinline__ void cp_async_commit() {
    asm volatile("cp.async.commit_group;" ::: "memory");
}
__device__ __forceinline__ float tanhfast(float z) {
    float r;
    asm("tanh.approx.f32 %0, %1;" : "=f"(r) : "f"(z));
    return r;
}
__device__ __forceinline__ float sigf(float z) {
    return fmaf(tanhfast(0.5f * z), 0.5f, 0.5f);
}

// ---------------------------------------------------------------- SMEM plan
// Row stride 400B: rows hit distinct bank quads -> conflict-free ldmatrix.
#define RS 400
#define OFF_BIAS 0
#define OFF_A    2048
#define OFF_B    (OFF_A + 128 * RS)     // 53248; two buffers of 25600
#define BUF_SZ   25600
#define SMEM_TC  (OFF_B + 2 * BUF_SZ)   // 104448 -> 2 CTAs/SM (16 warps/SM)

// ---------------------------------------------------------------- prep
__global__ void prep_kernel(const float* __restrict__ Wih,
                            const float* __restrict__ Whh,
                            const float* __restrict__ bih,
                            const float* __restrict__ bhh)
{
    int idx = blockIdx.x * blockDim.x + threadIdx.x;
    if (idx < 512) g_bsum[idx] = bih[idx] + bhh[idx];
    for (int p = idx; p < 512 * 192; p += gridDim.x * blockDim.x) {
        int g = p / 192, k = p - g * 192;
        float v = (k < 64) ? Wih[g * 64 + k] : Whh[g * 128 + (k - 64)];
        g_W[p] = __float2half_rn(v);
    }
}

// =====================================================================
// Tensor-core level kernel: CTA = 128 nodes x (512/gs) gates, 256 threads,
// 8 warps = 4 row-groups (32 nodes) x 2 chunk-halves, 2 CTAs/SM.
// Warp tile M=32 x N=32 -> LDSM:MMA = 1:2. Single-term fp16, fp32 accum.
// Gate-chunks of 64 independent; CTA handles cpc = 8/gs of them.
// c_prev prefetched to registers BEFORE the MMA loop (hides LDG latency).
// Leaf fast path: h_prev = 0 -> only k 0..63 (dk<2) AND B rows k<64 loaded.
// =====================================================================
__global__ __launch_bounds__(256, 2)
void lstm_tc_kernel(const float* __restrict__ x,
                    float* __restrict__ out,
                    int start, int isLeaf, int tiles, int cpc)
{
    extern __shared__ __align__(16) char smem[];
    const uint32_t sb = smem_u32(smem);
    const int tid = threadIdx.x;
    const int lane = tid & 31;
    const int rg = (tid >> 5) & 3;     // row group (32 nodes)
    const int ch = tid >> 7;           // chunk half (j-tiles 4ch..4ch+3)
    const int tile  = blockIdx.x % tiles;
    const int nc0   = (blockIdx.x / tiles) * cpc;   // first gate-chunk
    const int tileBase = tile * 128;

    float* bs = (float*)(smem + OFF_BIAS);
    for (int i = tid; i < 512; i += 256) bs[i] = g_bsum[i];

    // ---- A assembly: [128 rows][192 k] fp16 ----
    #pragma unroll
    for (int it = 0; it < 16; ++it) {              // x part: k 0..63 (convert)
        int p = tid + it * 256;
        int row = p >> 5;
        int kp  = (p & 31) * 2;
        int gnode = start + tileBase + row;
        float2 xv = *(const float2*)(x + (size_t)gnode * 64 + kp);
        __half2 hp = {__float2half_rn(xv.x), __float2half_rn(xv.y)};
        *(uint32_t*)(smem + OFF_A + row * RS + kp * 2) = *(uint32_t*)&hp;
    }
    if (!isLeaf) {                                  // h part: k 64..191, cp.async
        #pragma unroll
        for (int it = 0; it < 8; ++it) {
            int p = tid + it * 256;
            int row = p >> 4;
            int u   = p & 15;                       // 0..7 left, 8..15 right
            int gnode = start + tileBase + row;
            int child = (u < 8) ? (2 * gnode + 1) : (2 * gnode + 2);
            int uu = u & 7;
            cp_async16(sb + OFF_A + (uint32_t)(row * RS + 128 + u * 16),
                       g_hh + (size_t)child * 64 + uu * 8);
        }
    }
    // (leaf: k 64..191 never read -- dk loop and B loads bounded to x columns)

    // ---- B chunk prefetch into buf (24 uint4/row full, 8 leaf) ----
    auto issue_b = [&](int nc, int buf) {
        uint32_t bo = sb + OFF_B + (uint32_t)buf * BUF_SZ;
        if (isLeaf) {
            #pragma unroll
            for (int it = 0; it < 2; ++it) {
                int p = tid + it * 256;            // p < 512: 64 rows x 8 uint4
                int rr = p >> 3, u = p & 7;
                int j = rr >> 3, w = rr & 7;
                int gate = ((j & 3) << 7) + (nc << 4) + ((j >> 2) << 3) + w;
                cp_async16(bo + (uint32_t)(rr * RS + u * 16),
                           g_W + (size_t)gate * 192 + u * 8);
            }
        } else {
            #pragma unroll
            for (int it = 0; it < 6; ++it) {
                int p = tid + it * 256;            // p < 1536: 64 rows x 24
                int rr = p / 24, u = p - rr * 24;
                int j = rr >> 3, w = rr & 7;
                int gate = ((j & 3) << 7) + (nc << 4) + ((j >> 2) << 3) + w;
                cp_async16(bo + (uint32_t)(rr * RS + u * 16),
                           g_W + (size_t)gate * 192 + u * 8);
            }
        }
    };

    issue_b(nc0, 0);        // group 0 = A h-parts + B chunk nc0
    cp_async_commit();

    // per-lane ldmatrix bases
    const uint32_t aBase = sb + OFF_A +
        (uint32_t)((rg * 32 + (lane & 15)) * RS + ((lane >> 4) << 4));
    const uint32_t bBase = sb + OFF_B +
        (uint32_t)(ch * 32 * RS + (lane & 7) * RS + ((lane >> 3) << 4));
    const int r0   = rg * 32 + (lane >> 2);
    const int huL0 = (lane & 3) * 2;

    for (int l = 0; l < cpc; ++l) {
        const int nc = nc0 + l;
        asm volatile("cp.async.wait_group 0;" ::: "memory");  // buf l ready
        __syncthreads();   // all warps see buf l; prior reads of this slot done
        if (l + 1 < cpc) { // prefetch next chunk under this chunk's MMA
            issue_b(nc + 1, (l + 1) & 1);
            cp_async_commit();
        }

        const uint32_t bHi = bBase + (uint32_t)(l & 1) * BUF_SZ;
        const int hu = (nc << 4) + (ch << 3) + huL0;   // even pair {hu, hu+1}

        // ---- c_prev prefetch: LDGs fly under the MMA chain below ----
        float2 cpv[2][2];
        #pragma unroll
        for (int m = 0; m < 2; ++m)
            #pragma unroll
            for (int rh = 0; rh < 2; ++rh) {
                cpv[m][rh] = make_float2(0.f, 0.f);
                if (!isLeaf) {
                    int row = r0 + m * 16 + 8 * rh;
                    int gnode = start + tileBase + row;
                    int child = (hu < 64) ? (2 * gnode + 1) : (2 * gnode + 2);
                    cpv[m][rh] = *(const float2*)(g_c + (size_t)child * 64 + (hu & 63));
                }
            }

        float acc[2][4][4];
        #pragma unroll
        for (int m = 0; m < 2; ++m)
            #pragma unroll
            for (int j = 0; j < 4; ++j)
                #pragma unroll
                for (int c = 0; c < 4; ++c) acc[m][j][c] = 0.f;

        auto do_dk = [&](int dk) {
            uint32_t a0[2][4], a1[2][4];
            #pragma unroll
            for (int m = 0; m < 2; ++m) {
                ldsm_x4(a0[m], aBase + m * (16 * RS) + dk * 64);
                ldsm_x4(a1[m], aBase + m * (16 * RS) + dk * 64 + 32);
            }
            #pragma unroll
            for (int jj = 0; jj < 4; ++jj) {
                uint32_t bh[4];
                ldsm_x4(bh, bHi + jj * (8 * RS) + dk * 64);
                #pragma unroll
                for (int m = 0; m < 2; ++m) {
                    mma_f16(acc[m][jj], a0[m], bh);
                    mma_f16(acc[m][jj], a1[m], bh + 2);
                }
            }
        };
        if (isLeaf) {
            #pragma unroll
            for (int dk = 0; dk < 2; ++dk) do_dk(dk);   // x columns only
        } else {
            #pragma unroll
            for (int dk = 0; dk < 6; ++dk) do_dk(dk);
        }

        // ---- fused LSTM epilogue: this warp owns full (i,f,g,o) quad ----
        #pragma unroll
        for (int m = 0; m < 2; ++m) {
            #pragma unroll
            for (int rh = 0; rh < 2; ++rh) {
                const int row = r0 + m * 16 + 8 * rh;
                const int gnode = start + tileBase + row;
                float2 cp = cpv[m][rh];
                float gi0 = acc[m][0][2 * rh]     + bs[hu];
                float gi1 = acc[m][0][2 * rh + 1] + bs[hu + 1];
                float gf0 = acc[m][1][2 * rh]     + bs[128 + hu];
                float gf1 = acc[m][1][2 * rh + 1] + bs[128 + hu + 1];
                float gg0 = acc[m][2][2 * rh]     + bs[256 + hu];
                float gg1 = acc[m][2][2 * rh + 1] + bs[256 + hu + 1];
                float go0 = acc[m][3][2 * rh]     + bs[384 + hu];
                float go1 = acc[m][3][2 * rh + 1] + bs[384 + hu + 1];
                float c0 = sigf(gf0) * cp.x + sigf(gi0) * tanhfast(gg0);
                float c1 = sigf(gf1) * cp.y + sigf(gi1) * tanhfast(gg1);
                float h0 = sigf(go0) * tanhfast(c0);
                float h1 = sigf(go1) * tanhfast(c1);
                *(float2*)(out + (size_t)gnode * 128 + hu) = make_float2(h0, h1);
                if (hu < 64) {
                    *(float2*)(g_c + (size_t)gnode * 64 + hu) = make_float2(c0, c1);
                    __half2 hp = {__float2half_rn(h0), __float2half_rn(h1)};
                    *(uint32_t*)(g_hh + (size_t)gnode * 64 + hu) = *(uint32_t*)&hp;
                }
            }
        }
    }
}

// =====================================================================
// Small-level SIMT kernel: 8 nodes per 256-thread block (128 <= count < 1024).
// =====================================================================
__global__ __launch_bounds__(256, 4)
void lstm_small_kernel(const float* __restrict__ x,
                       const float* __restrict__ Wih,
                       const float* __restrict__ Whh,
                       const float* __restrict__ bih,
                       const float* __restrict__ bhh,
                       float* __restrict__ out,
                       int start, int count)
{
    __shared__ __align__(16) float As[8][196];
    __shared__ __align__(16) float Cs[8][128];
    __shared__ float bsm[512];

    const int t = threadIdx.x;
    const int tileBase = blockIdx.x * 8;

    for (int i = t; i < 512; i += 256) bsm[i] = bih[i] + bhh[i];

    for (int q = t; q < 384; q += 256) {
        int node = q / 48, c4 = q - node * 48, col = c4 * 4;
        float4 v = make_float4(0.f, 0.f, 0.f, 0.f);
        int nodeIdx = tileBase + node;
        if (nodeIdx < count) {
            int gnode = start + nodeIdx;
            if (col < 64) {
                v = *(const float4*)(x + (size_t)gnode * 64 + col);
            } else {
                int child = (col < 128) ? (2 * gnode + 1) : (2 * gnode + 2);
                int cc    = (col < 128) ? (col - 64) : (col - 128);
                v = *(const float4*)(out + (size_t)child * 128 + cc);
            }
        }
        *(float4*)&As[node][col] = v;
    }
    {
        int node = t / 32, col = (t & 31) * 4;
        float4 v = make_float4(0.f, 0.f, 0.f, 0.f);
        int nodeIdx = tileBase + node;
        if (nodeIdx < count) {
            int gnode = start + nodeIdx;
            int child = (col < 64) ? (2 * gnode + 1) : (2 * gnode + 2);
            int cc    = (col < 64) ? col : (col - 64);
            v = *(const float4*)&g_c[(size_t)child * 64 + cc];
        }
        *(float4*)&Cs[node][col] = v;
    }
    __syncthreads();

    const int hu = t & 127;
    const int np = t >> 7;
    float acc[4][4];
    #pragma unroll
    for (int n = 0; n < 4; ++n)
        #pragma unroll
        for (int g = 0; g < 4; ++g)
            acc[n][g] = bsm[hu + g * 128];

    for (int kc = 0; kc < 48; ++kc) {
        const int k0 = kc * 4;
        float4 w[4];
        #pragma unroll
        for (int g = 0; g < 4; ++g) {
            int grow = hu + g * 128;
            w[g] = (k0 < 64)
                 ? *(const float4*)(Wih + (size_t)grow * 64 + k0)
                 : *(const float4*)(Whh + (size_t)grow * 128 + (k0 - 64));
        }
        #pragma unroll
        for (int n = 0; n < 4; ++n) {
            float4 a = *(const float4*)&As[np + 2 * n][k0];
            #pragma unroll
            for (int g = 0; g < 4; ++g)
                acc[n][g] += a.x * w[g].x + a.y * w[g].y + a.z * w[g].z + a.w * w[g].w;
        }
    }

    #pragma unroll
    for (int n = 0; n < 4; ++n) {
        int nn = np + 2 * n;
        int nodeIdx = tileBase + nn;
        if (nodeIdx < count) {
            int gnode = start + nodeIdx;
            float cp = Cs[nn][hu];
            float c = sigf(acc[n][1]) * cp + sigf(acc[n][0]) * tanhfast(acc[n][2]);
            float h = sigf(acc[n][3]) * tanhfast(c);
            out[(size_t)gnode * 128 + hu] = h;
            if (hu < 64) g_c[(size_t)gnode * 64 + hu] = c;
        }
    }
}

// =====================================================================
// Tiny-level kernel (count <= 64): 1 block = 1 node, 256 threads,
// thread computes 2 full gate dot-products (K=192) in fp32.
// =====================================================================
__global__ __launch_bounds__(256, 4)
void lstm_tiny_kernel(const float* __restrict__ x,
                      const float* __restrict__ Wih,
                      const float* __restrict__ Whh,
                      const float* __restrict__ bih,
                      const float* __restrict__ bhh,
                      float* __restrict__ out,
                      int start)
{
    __shared__ __align__(16) float A[192];
    __shared__ __align__(16) float Cp[128];
    __shared__ float gates[512];

    const int t = threadIdx.x;
    const int gnode = start + blockIdx.x;

    if (t < 192) {
        if (t < 64) {
            A[t] = x[(size_t)gnode * 64 + t];
        } else {
            int k = t - 64;
            int child = (k < 64) ? (2 * gnode + 1) : (2 * gnode + 2);
            A[t] = out[(size_t)child * 128 + (k & 63)];
        }
    }
    if (t < 128) {
        int child = (t < 64) ? (2 * gnode + 1) : (2 * gnode + 2);
        Cp[t] = g_c[(size_t)child * 64 + (t & 63)];
    }
    __syncthreads();

    #pragma unroll
    for (int gg = 0; gg < 2; ++gg) {
        int g = t + gg * 256;
        float acc = bih[g] + bhh[g];
        const float* wx = Wih + (size_t)g * 64;
        const float* wh = Whh + (size_t)g * 128;
        #pragma unroll
        for (int k = 0; k < 64; k += 4) {
            float4 w = *(const float4*)(wx + k);
            acc += w.x * A[k] + w.y * A[k + 1] + w.z * A[k + 2] + w.w * A[k + 3];
        }
        #pragma unroll
        for (int k = 0; k < 128; k += 4) {
            float4 w = *(const float4*)(wh + k);
            acc += w.x * A[64 + k] + w.y * A[65 + k] + w.z * A[66 + k] + w.w * A[67 + k];
        }
        gates[g] = acc;
    }
    __syncthreads();

    if (t < 128) {
        float c = sigf(gates[128 + t]) * Cp[t] + sigf(gates[t]) * tanhfast(gates[256 + t]);
        float h = sigf(gates[384 + t]) * tanhfast(c);
        out[(size_t)gnode * 128 + t] = h;
        if (t < 64) g_c[(size_t)gnode * 64 + t] = c;
    }
}

extern "C" void kernel_launch(void* const* d_in, const int* in_sizes, int n_in,
                              void* d_out, int out_size)
{
    const float* x   = (const float*)d_in[0];   // [262143, 64]
    const float* Wih = (const float*)d_in[1];   // [512, 64]
    const float* Whh = (const float*)d_in[2];   // [512, 128]
    const float* bih = (const float*)d_in[3];   // [512]
    const float* bhh = (const float*)d_in[4];   // [512]
    float* out = (float*)d_out;                 // [262143, 128]

    static bool attr_done = false;
    if (!attr_done) {
        cudaFuncSetAttribute(lstm_tc_kernel,
                             cudaFuncAttributeMaxDynamicSharedMemorySize, SMEM_TC);
        attr_done = true;
    }

    prep_kernel<<<96, 256>>>(Wih, Whh, bih, bhh);

    const int CONC = 296;   // 148 SMs x 2 CTAs
    for (int lvl = LEVELS - 1; lvl >= 0; --lvl) {
        int start = (1 << lvl) - 1;
        int count = 1 << lvl;
        int isLeaf = (lvl == LEVELS - 1);
        if (count >= 1024) {
            int tiles = count / 128;
            int gs = 1;
            while (gs < 8 && tiles * gs * 2 <= CONC) gs <<= 1;  // fill, 1 wave
            lstm_tc_kernel<<<tiles * gs, 256, SMEM_TC>>>(
                x, out, start, isLeaf, tiles, 8 / gs);
        } else if (count >= 128) {
            lstm_small_kernel<<<count / 8, 256>>>(
                x, Wih, Whh, bih, bhh, out, start, count);
        } else {
            lstm_tiny_kernel<<<count, 256>>>(
                x, Wih, Whh, bih, bhh, out, start);
        }
    }
}